// round 15
// baseline (speedup 1.0000x reference)
#include <cuda_runtime.h>
#include <cuda_bf16.h>
#include <cstdint>
#include <math.h>

#define B      64
#define HID    768
#define VOCAB  50257
#define MAXLEN 32
#define GATES  (4*HID)
#define KCAT   (2*HID)
#define SOS    1
#define OSTRIDE ((long long)MAXLEN*VOCAB)

// ---- gates kernel stage layout (K64 chunks, 144B rows) ----
#define ROW_U4   9
#define ROW_ELEM 72
#define STAGE_U4 3456
#define STAGE_EL 27648
#define XLO_EL   4608
#define WHI_EL   9216
#define DSMEM_G  (2*STAGE_U4*16)   // 110592

// ---- logits kernel: M64 x N384 tile, K32 chunks, 80B rows, 3 stages, 1 CTA/SM ----
#define L_ROW_EL 40
#define L_ROW_U4 5
#define L_STG_U4 4480              // X 640 u4 + W 3840 u4
#define L_STG_EL 35840
#define L_XLO    2560              // X lo plane offset (elems) = 64*40
#define L_WHI    5120              // W region offset (elems)  = 640*8
#define L_WSPAN  15360             // W plane span (elems)     = 384*40
#define DSMEM_L  (3*L_STG_U4*16)   // 215040

typedef unsigned int u32;
typedef unsigned long long u64;

// ---------------- device-global state ----------------
__device__ float g_h[B*HID];
__device__ float g_c[B*HID];
__device__ float g_gates[B*GATES];
__device__ float g_bgate[GATES];
__device__ u64   g_key[B];

__device__ uint4 g_WhiR[((size_t)VOCAB*HID)/8];
__device__ uint4 g_WloR[((size_t)VOCAB*HID)/8];
__device__ uint4 g_WchiR[((size_t)GATES*KCAT)/8];
__device__ uint4 g_WcloR[((size_t)GATES*KCAT)/8];
__device__ uint4 g_hhiR[(B*HID)/8];
__device__ uint4 g_hloR[(B*HID)/8];

#define G_WHI  ((__nv_bfloat16*)g_WhiR)
#define G_WLO  ((__nv_bfloat16*)g_WloR)
#define G_WCHI ((__nv_bfloat16*)g_WchiR)
#define G_WCLO ((__nv_bfloat16*)g_WcloR)
#define G_HHI  ((__nv_bfloat16*)g_hhiR)
#define G_HLO  ((__nv_bfloat16*)g_hloR)

__device__ __forceinline__ void split2(float v, __nv_bfloat16* hi, __nv_bfloat16* lo) {
    __nv_bfloat16 h = __float2bfloat16_rn(v);
    *hi = h;
    *lo = __float2bfloat16_rn(v - __bfloat162float(h));
}

__device__ __forceinline__ u64 packKey(float v, int n) {
    u32 u = __float_as_uint(v);
    if (u & 0x80000000u) { u = ~u; } else { u = u | 0x80000000u; }
    return (((u64)u) << 32) | (u64)(0xFFFFFFFFu - (u32)n);
}

__device__ __forceinline__ void ldsm4(u32* r, const __nv_bfloat16* p) {
    u32 a = (u32)__cvta_generic_to_shared(p);
    asm volatile("ldmatrix.sync.aligned.m8n8.x4.shared.b16 {%0,%1,%2,%3},[%4];"
                 : "=r"(r[0]), "=r"(r[1]), "=r"(r[2]), "=r"(r[3]) : "r"(a));
}

__device__ __forceinline__ void mma16816(float* d, const u32* a, u32 b0, u32 b1) {
    asm volatile("mma.sync.aligned.m16n8k16.row.col.f32.bf16.bf16.f32 "
                 "{%0,%1,%2,%3},{%4,%5,%6,%7},{%8,%9},{%0,%1,%2,%3};"
                 : "+f"(d[0]), "+f"(d[1]), "+f"(d[2]), "+f"(d[3])
                 : "r"(a[0]), "r"(a[1]), "r"(a[2]), "r"(a[3]), "r"(b0), "r"(b1));
}

__device__ __forceinline__ void cp16(void* dst, const void* src) {
    u32 d = (u32)__cvta_generic_to_shared(dst);
    asm volatile("cp.async.cg.shared.global [%0], [%1], 16;\n" :: "r"(d), "l"(src));
}

// ---------------- init ----------------
__global__ void k_init(const float* __restrict__ W_ih, const float* __restrict__ W_hh,
                       const float* __restrict__ b_ih, const float* __restrict__ b_hh,
                       const float* __restrict__ W_out) {
    size_t tid = (size_t)blockIdx.x * blockDim.x + threadIdx.x;
    size_t stride = (size_t)gridDim.x * blockDim.x;
    for (size_t i = tid; i < (size_t)VOCAB * HID; i += stride) {
        split2(W_out[i], &G_WHI[i], &G_WLO[i]);
    }
    for (size_t i = tid; i < (size_t)GATES * KCAT; i += stride) {
        int j = (int)(i / KCAT);
        int k = (int)(i - (size_t)j * KCAT);
        float v;
        if (k < HID) { v = W_ih[(size_t)j * HID + k]; }
        else         { v = W_hh[(size_t)j * HID + (k - HID)]; }
        split2(v, &G_WCHI[i], &G_WCLO[i]);
    }
    for (size_t i = tid; i < GATES; i += stride) { g_bgate[i] = b_ih[i] + b_hh[i]; }
    for (size_t i = tid; i < B * HID; i += stride) { g_h[i] = 0.f; g_c[i] = 0.f; }
    for (size_t i = tid; i < (size_t)B * GATES; i += stride) { g_gates[i] = 0.f; }
    if (tid < B) { g_key[tid] = (u64)(0xFFFFFFFFu - (u32)SOS); }
}

// prefetch one K32 chunk into stage s (logits, N384): 512 X cp16 + 3072 W cp16 = 14/thread
__device__ __forceinline__ void pf_logits(uint4* Sm4, int nbase, int kc, int s, int tid) {
    int su = s * L_STG_U4;
    #pragma unroll
    for (int e = 0; e < 2; e++) {
        int lin = tid + e * 256;
        int plane = lin >> 8;
        int idx = lin & 255;
        int r = idx >> 2;
        int col = idx & 3;
        const __nv_bfloat16* src = plane ? &G_HLO[r * HID + kc + col * 8]
                                         : &G_HHI[r * HID + kc + col * 8];
        cp16(&Sm4[su + plane * 320 + r * L_ROW_U4 + col], src);
    }
    #pragma unroll
    for (int e = 0; e < 12; e++) {
        int lin = tid + e * 256;
        int plane = (lin >= 1536) ? 1 : 0;
        int idx = lin - plane * 1536;
        int rr = idx >> 2;
        int col = idx & 3;
        int n = nbase + rr;
        if (n > VOCAB - 1) { n = VOCAB - 1; }
        const __nv_bfloat16* src = plane ? &G_WLO[(size_t)n * HID + kc + col * 8]
                                         : &G_WHI[(size_t)n * HID + kc + col * 8];
        cp16(&Sm4[su + 640 + plane * 1920 + rr * L_ROW_U4 + col], src);
    }
    asm volatile("cp.async.commit_group;\n");
}

// ---------------- logits: C[64][VOCAB] = h @ W_out^T + b, fused argmax ----------------
// M64 x N384 (warp M32 x N96), K32 chunks, 3-stage cp.async wait_group(1), grid=131 (1 wave).
__global__ void __launch_bounds__(256, 1) k_logits(const float* __restrict__ bias,
                                                   float* __restrict__ outStep) {
    extern __shared__ uint4 Sm4[];
    __shared__ u64 skey[64];
    const __nv_bfloat16* Sm = (const __nv_bfloat16*)Sm4;

    int tid = threadIdx.x;
    int w = tid >> 5;
    int l = tid & 31;
    int wm = w >> 2;                 // 0..1
    int wn = w & 3;                  // 0..3
    int nbase = blockIdx.x * 384;
    if (tid < 64) { skey[tid] = 0ull; }

    int sub = l >> 3;
    int arow = (sub & 1) * 8 + (l & 7);
    int acolo = (sub >> 1) * 8;
    int brow = (sub >> 1) * 8 + (l & 7);
    int bcolo = (sub & 1) * 8;

    float acc[2][12][4];
    #pragma unroll
    for (int i = 0; i < 2; i++) {
        #pragma unroll
        for (int j = 0; j < 12; j++) {
            #pragma unroll
            for (int q = 0; q < 4; q++) { acc[i][j][q] = 0.f; }
        }
    }

    pf_logits(Sm4, nbase, 0, 0, tid);
    pf_logits(Sm4, nbase, 32, 1, tid);

    #pragma unroll 1
    for (int c = 0; c < 24; c++) {
        if (c < 23) { asm volatile("cp.async.wait_group 1;\n"); }
        else        { asm volatile("cp.async.wait_group 0;\n"); }
        __syncthreads();
        if (c + 2 < 24) {
            int ns = (c + 2) % 3;
            pf_logits(Sm4, nbase, (c + 2) * 32, ns, tid);
        }

        int s = c % 3;
        const __nv_bfloat16* Xb = Sm + s * L_STG_EL;
        const __nv_bfloat16* Wb = Sm + s * L_STG_EL + L_WHI;
        #pragma unroll
        for (int kk = 0; kk < 2; kk++) {
            int kb = kk * 16;
            u32 ah[2][4];
            u32 al[2][4];
            #pragma unroll
            for (int mt = 0; mt < 2; mt++) {
                int r = wm * 32 + mt * 16 + arow;
                ldsm4(ah[mt], Xb + r * L_ROW_EL + kb + acolo);
                ldsm4(al[mt], Xb + L_XLO + r * L_ROW_EL + kb + acolo);
            }
            #pragma unroll
            for (int ntp = 0; ntp < 6; ntp++) {
                u32 bh[4];
                u32 bl[4];
                int rw = wn * 96 + ntp * 16 + brow;
                ldsm4(bh, Wb + rw * L_ROW_EL + kb + bcolo);
                ldsm4(bl, Wb + L_WSPAN + rw * L_ROW_EL + kb + bcolo);
                #pragma unroll
                for (int half = 0; half < 2; half++) {
                    int nt = ntp * 2 + half;
                    u32 h0 = bh[half * 2];
                    u32 h1 = bh[half * 2 + 1];
                    u32 lo0 = bl[half * 2];
                    u32 lo1 = bl[half * 2 + 1];
                    #pragma unroll
                    for (int mt = 0; mt < 2; mt++) {
                        mma16816(acc[mt][nt], ah[mt], h0, h1);
                        mma16816(acc[mt][nt], ah[mt], lo0, lo1);
                        mma16816(acc[mt][nt], al[mt], h0, h1);
                    }
                }
            }
        }
    }

    // epilogue: bias + store + argmax keys
    #pragma unroll
    for (int mt = 0; mt < 2; mt++) {
        int r = wm * 32 + mt * 16 + (l >> 2);
        u64 k0 = 0ull;
        u64 k1 = 0ull;
        #pragma unroll
        for (int nt = 0; nt < 12; nt++) {
            int c0 = nbase + wn * 96 + nt * 8 + (l & 3) * 2;
            if (c0 + 1 < VOCAB) {
                const float2* bp = reinterpret_cast<const float2*>(&bias[c0]);
                float2 bb = bp[0];
                float v0 = acc[mt][nt][0] + bb.x;
                float v1 = acc[mt][nt][1] + bb.y;
                float v2 = acc[mt][nt][2] + bb.x;
                float v3 = acc[mt][nt][3] + bb.y;
                outStep[(long long)r * OSTRIDE + c0]           = v0;
                outStep[(long long)r * OSTRIDE + c0 + 1]       = v1;
                outStep[(long long)(r + 8) * OSTRIDE + c0]     = v2;
                outStep[(long long)(r + 8) * OSTRIDE + c0 + 1] = v3;
                u64 t;
                t = packKey(v0, c0);     if (t > k0) { k0 = t; }
                t = packKey(v1, c0 + 1); if (t > k0) { k0 = t; }
                t = packKey(v2, c0);     if (t > k1) { k1 = t; }
                t = packKey(v3, c0 + 1); if (t > k1) { k1 = t; }
            } else if (c0 < VOCAB) {
                float bb = bias[c0];
                float v0 = acc[mt][nt][0] + bb;
                float v2 = acc[mt][nt][2] + bb;
                outStep[(long long)r * OSTRIDE + c0]       = v0;
                outStep[(long long)(r + 8) * OSTRIDE + c0] = v2;
                u64 t;
                t = packKey(v0, c0); if (t > k0) { k0 = t; }
                t = packKey(v2, c0); if (t > k1) { k1 = t; }
            }
        }
        #pragma unroll
        for (int s = 1; s <= 2; s <<= 1) {
            u64 o0 = __shfl_xor_sync(0xFFFFFFFFu, k0, s);
            u64 o1 = __shfl_xor_sync(0xFFFFFFFFu, k1, s);
            if (o0 > k0) { k0 = o0; }
            if (o1 > k1) { k1 = o1; }
        }
        if ((l & 3) == 0) {
            atomicMax(&skey[r], k0);
            atomicMax(&skey[r + 8], k1);
        }
    }
    __syncthreads();
    if (tid < 64) {
        if (skey[tid] != 0ull) { atomicMax(&g_key[tid], skey[tid]); }
    }
}

// gather x[b][k] (k<HID: emb[tok], else h) -> split hi/lo uint4 (8 elems)
__device__ __forceinline__ void gatherx(int lm, int lk, int kc, const float* __restrict__ emb,
                                        const int* stoks, uint4& xh, uint4& xl) {
    int k = kc + lk;
    const float* src;
    if (k < HID) { src = emb + (size_t)stoks[lm] * HID + k; }
    else         { src = g_h + lm * HID + (k - HID); }
    float4 f0 = *reinterpret_cast<const float4*>(src);
    float4 f1 = *reinterpret_cast<const float4*>(src + 4);
    float v[8] = {f0.x, f0.y, f0.z, f0.w, f1.x, f1.y, f1.z, f1.w};
    u32 hw[4];
    u32 lw[4];
    #pragma unroll
    for (int e = 0; e < 4; e++) {
        __nv_bfloat16 h0, l0, h1, l1;
        split2(v[2 * e], &h0, &l0);
        split2(v[2 * e + 1], &h1, &l1);
        __nv_bfloat162 hp;
        hp.x = h0; hp.y = h1;
        __nv_bfloat162 lp;
        lp.x = l0; lp.y = l1;
        hw[e] = *reinterpret_cast<u32*>(&hp);
        lw[e] = *reinterpret_cast<u32*>(&lp);
    }
    xh = make_uint4(hw[0], hw[1], hw[2], hw[3]);
    xl = make_uint4(lw[0], lw[1], lw[2], lw[3]);
}

// prefetch one K64 chunk (gates): W via cp.async, X via gather+STS
__device__ __forceinline__ void pf_gates(uint4* Sm4, int nbase, int kc, int s, int tid,
                                         const float* __restrict__ emb, const int* stoks) {
    #pragma unroll
    for (int e = 0; e < 4; e++) {
        int lin = tid + e * 256;
        int row = lin >> 3;
        int cc = lin & 7;
        int n = nbase + row;
        cp16(&Sm4[s * STAGE_U4 + 1152 + row * ROW_U4 + cc], &G_WCHI[(size_t)n * KCAT + kc + cc * 8]);
        cp16(&Sm4[s * STAGE_U4 + 2304 + row * ROW_U4 + cc], &G_WCLO[(size_t)n * KCAT + kc + cc * 8]);
    }
    asm volatile("cp.async.commit_group;\n");
    #pragma unroll
    for (int e = 0; e < 2; e++) {
        int lin = tid + e * 256;
        int row = lin >> 3;
        int cc = lin & 7;
        uint4 xh, xl;
        gatherx(row, cc * 8, kc, emb, stoks, xh, xl);
        Sm4[s * STAGE_U4 + row * ROW_U4 + cc] = xh;
        Sm4[s * STAGE_U4 + 576 + row * ROW_U4 + cc] = xl;
    }
}

// ---------------- gates: g_gates[64][3072] += [emb|h] @ Wcat^T (+b on split 0) ----------------
__global__ void __launch_bounds__(256, 2) k_gates(const float* __restrict__ emb) {
    extern __shared__ uint4 Sm4[];
    __shared__ int stoks[64];
    const __nv_bfloat16* Sm = (const __nv_bfloat16*)Sm4;

    int tid = threadIdx.x;
    int w = tid >> 5;
    int l = tid & 31;
    int wm = w >> 2;
    int wn = w & 3;
    int nbase = blockIdx.x * 128;
    int kBegin = blockIdx.y * 192;

    if (tid < 64) {
        stoks[tid] = (int)(0xFFFFFFFFu - (u32)(g_key[tid] & 0xFFFFFFFFull));
    }
    __syncthreads();

    int sub = l >> 3;
    int arow = (sub & 1) * 8 + (l & 7);
    int acolo = (sub >> 1) * 8;
    int brow = (sub >> 1) * 8 + (l & 7);
    int bcolo = (sub & 1) * 8;

    float acc[2][4][4];
    #pragma unroll
    for (int i = 0; i < 2; i++) {
        #pragma unroll
        for (int j = 0; j < 4; j++) {
            #pragma unroll
            for (int q = 0; q < 4; q++) { acc[i][j][q] = 0.f; }
        }
    }

    pf_gates(Sm4, nbase, kBegin, 0, tid, emb, stoks);

    #pragma unroll 1
    for (int c = 0; c < 3; c++) {
        asm volatile("cp.async.wait_group 0;\n");
        __syncthreads();
        if (c < 2) { pf_gates(Sm4, nbase, kBegin + (c + 1) * 64, (c + 1) & 1, tid, emb, stoks); }

        int s = c & 1;
        const __nv_bfloat16* Xb = Sm + s * STAGE_EL;
        const __nv_bfloat16* Wb = Sm + s * STAGE_EL + WHI_EL;
        #pragma unroll
        for (int kk = 0; kk < 4; kk++) {
            int kb = kk * 16;
            u32 ah[2][4];
            u32 al[2][4];
            #pragma unroll
            for (int mt = 0; mt < 2; mt++) {
                int r = wm * 32 + mt * 16 + arow;
                ldsm4(ah[mt], Xb + r * ROW_ELEM + kb + acolo);
                ldsm4(al[mt], Xb + XLO_EL + r * ROW_ELEM + kb + acolo);
            }
            u32 bh[2][4];
            u32 bl[2][4];
            #pragma unroll
            for (int ntp = 0; ntp < 2; ntp++) {
                int r = wn * 32 + ntp * 16 + brow;
                ldsm4(bh[ntp], Wb + r * ROW_ELEM + kb + bcolo);
                ldsm4(bl[ntp], Wb + WHI_EL + r * ROW_ELEM + kb + bcolo);
            }
            #pragma unroll
            for (int nt = 0; nt < 4; nt++) {
                int ntp = nt >> 1;
                int hf = (nt & 1) * 2;
                u32 h0 = bh[ntp][hf];
                u32 h1 = bh[ntp][hf + 1];
                u32 lo0 = bl[ntp][hf];
                u32 lo1 = bl[ntp][hf + 1];
                #pragma unroll
                for (int mt = 0; mt < 2; mt++) {
                    mma16816(acc[mt][nt], ah[mt], h0, h1);
                    mma16816(acc[mt][nt], ah[mt], lo0, lo1);
                    mma16816(acc[mt][nt], al[mt], h0, h1);
                }
            }
        }
    }

    bool ab = (blockIdx.y == 0);
    #pragma unroll
    for (int mt = 0; mt < 2; mt++) {
        int r = wm * 32 + mt * 16 + (l >> 2);
        #pragma unroll
        for (int nt = 0; nt < 4; nt++) {
            int c0 = nbase + wn * 32 + nt * 8 + (l & 3) * 2;
            float bb0 = 0.f;
            float bb1 = 0.f;
            if (ab) { bb0 = g_bgate[c0]; bb1 = g_bgate[c0 + 1]; }
            atomicAdd(&g_gates[r * GATES + c0],           acc[mt][nt][0] + bb0);
            atomicAdd(&g_gates[r * GATES + c0 + 1],       acc[mt][nt][1] + bb1);
            atomicAdd(&g_gates[(r + 8) * GATES + c0],     acc[mt][nt][2] + bb0);
            atomicAdd(&g_gates[(r + 8) * GATES + c0 + 1], acc[mt][nt][3] + bb1);
        }
    }
}

// ---------------- LSTM cell update (float4) + zero gates + reset argmax ----------------
__global__ void k_update() {
    int idx = blockIdx.x * blockDim.x + threadIdx.x;
    if (idx < (B * HID) / 4) {
        int e = idx * 4;
        int b = e / HID;
        int j = e - b * HID;
        float* gr = &g_gates[b * GATES];
        float4 gi = *reinterpret_cast<float4*>(&gr[j]);
        float4 gf = *reinterpret_cast<float4*>(&gr[HID + j]);
        float4 gg = *reinterpret_cast<float4*>(&gr[2 * HID + j]);
        float4 go = *reinterpret_cast<float4*>(&gr[3 * HID + j]);
        float4 zz = make_float4(0.f, 0.f, 0.f, 0.f);
        *reinterpret_cast<float4*>(&gr[j]) = zz;
        *reinterpret_cast<float4*>(&gr[HID + j]) = zz;
        *reinterpret_cast<float4*>(&gr[2 * HID + j]) = zz;
        *reinterpret_cast<float4*>(&gr[3 * HID + j]) = zz;
        float4 cp = *reinterpret_cast<float4*>(&g_c[e]);
        float ia[4] = {gi.x, gi.y, gi.z, gi.w};
        float fa[4] = {gf.x, gf.y, gf.z, gf.w};
        float ga[4] = {gg.x, gg.y, gg.z, gg.w};
        float oa[4] = {go.x, go.y, go.z, go.w};
        float ca[4] = {cp.x, cp.y, cp.z, cp.w};
        float hn[4];
        float cn[4];
        #pragma unroll
        for (int q = 0; q < 4; q++) {
            float iv = 1.f / (1.f + expf(-ia[q]));
            float fv = 1.f / (1.f + expf(-fa[q]));
            float gv = tanhf(ga[q]);
            float ov = 1.f / (1.f + expf(-oa[q]));
            float c = fv * ca[q] + iv * gv;
            cn[q] = c;
            hn[q] = ov * tanhf(c);
        }
        *reinterpret_cast<float4*>(&g_c[e]) = make_float4(cn[0], cn[1], cn[2], cn[3]);
        *reinterpret_cast<float4*>(&g_h[e]) = make_float4(hn[0], hn[1], hn[2], hn[3]);
        #pragma unroll
        for (int q = 0; q < 4; q++) {
            split2(hn[q], &G_HHI[e + q], &G_HLO[e + q]);
        }
    }
    if (idx < B) { g_key[idx] = 0ull; }
}

__global__ void k_final(float* __restrict__ out) {
    int idx = blockIdx.x * blockDim.x + threadIdx.x;
    if (idx < B * HID) {
        out[idx]           = g_h[idx];
        out[B * HID + idx] = g_c[idx];
    }
}

extern "C" void kernel_launch(void* const* d_in, const int* in_sizes, int n_in,
                              void* d_out, int out_size) {
    const float* emb   = (const float*)d_in[1];
    const float* W_ih  = (const float*)d_in[2];
    const float* W_hh  = (const float*)d_in[3];
    const float* b_ih  = (const float*)d_in[4];
    const float* b_hh  = (const float*)d_in[5];
    const float* W_out = (const float*)d_in[6];
    const float* b_out = (const float*)d_in[7];
    float* out = (float*)d_out;

    cudaFuncSetAttribute(k_logits, cudaFuncAttributeMaxDynamicSharedMemorySize, DSMEM_L);
    cudaFuncSetAttribute(k_gates, cudaFuncAttributeMaxDynamicSharedMemorySize, DSMEM_G);

    k_init<<<2048, 256>>>(W_ih, W_hh, b_ih, b_hh, W_out);

    const long long logitsSize = (long long)B * MAXLEN * VOCAB;
    for (int t = 0; t < MAXLEN; t++) {
        k_gates<<<dim3(GATES / 128, 8), 256, DSMEM_G>>>(emb);
        k_update<<<48, 256>>>();
        k_logits<<<(VOCAB + 383) / 384, 256, DSMEM_L>>>(b_out, out + (long long)t * VOCAB);
    }
    if ((long long)out_size >= logitsSize + 2LL * B * HID) {
        k_final<<<192, 256>>>(out + logitsSize);
    }
}

// round 17
// speedup vs baseline: 1.0956x; 1.0956x over previous
#include <cuda_runtime.h>
#include <cuda_bf16.h>
#include <cstdint>
#include <math.h>

#define B      64
#define HID    768
#define VOCAB  50257
#define MAXLEN 32
#define GATES  (4*HID)
#define KCAT   (2*HID)
#define SOS    1
#define OSTRIDE ((long long)MAXLEN*VOCAB)

// ---- gates kernel stage layout (K64 chunks, 144B rows) ----
#define ROW_U4   9
#define ROW_ELEM 72
#define STAGE_U4 3456
#define STAGE_EL 27648
#define XLO_EL   4608
#define WHI_EL   9216
#define DSMEM_G  (2*STAGE_U4*16)   // 110592

// ---- logits kernel: M64 x N192 tile, K32 chunks (2 x K16 half-commits), 80B rows, 2 stages ----
#define L_ROW_EL 40
#define L_ROW_U4 5
#define L_STG_EL 20480
#define L_STG_U4 2560
#define L_XLO    2560              // X lo plane offset (elems)
#define L_WHI    5120              // W region offset (elems)
#define L_WSPAN  7680              // W plane span (192 rows * 40)
#define DSMEM_L  (2*L_STG_U4*16)   // 81920

typedef unsigned int u32;
typedef unsigned long long u64;

// ---------------- device-global state ----------------
__device__ float g_h[B*HID];
__device__ float g_c[B*HID];
__device__ float g_gates[B*GATES];
__device__ float g_bgate[GATES];
__device__ u64   g_key[B];

__device__ uint4 g_WhiR[((size_t)VOCAB*HID)/8];
__device__ uint4 g_WloR[((size_t)VOCAB*HID)/8];
__device__ uint4 g_WchiR[((size_t)GATES*KCAT)/8];
__device__ uint4 g_WcloR[((size_t)GATES*KCAT)/8];
__device__ uint4 g_hhiR[(B*HID)/8];
__device__ uint4 g_hloR[(B*HID)/8];

#define G_WHI  ((__nv_bfloat16*)g_WhiR)
#define G_WLO  ((__nv_bfloat16*)g_WloR)
#define G_WCHI ((__nv_bfloat16*)g_WchiR)
#define G_WCLO ((__nv_bfloat16*)g_WcloR)
#define G_HHI  ((__nv_bfloat16*)g_hhiR)
#define G_HLO  ((__nv_bfloat16*)g_hloR)

__device__ __forceinline__ void split2(float v, __nv_bfloat16* hi, __nv_bfloat16* lo) {
    __nv_bfloat16 h = __float2bfloat16_rn(v);
    *hi = h;
    *lo = __float2bfloat16_rn(v - __bfloat162float(h));
}

__device__ __forceinline__ u64 packKey(float v, int n) {
    u32 u = __float_as_uint(v);
    if (u & 0x80000000u) { u = ~u; } else { u = u | 0x80000000u; }
    return (((u64)u) << 32) | (u64)(0xFFFFFFFFu - (u32)n);
}

__device__ __forceinline__ void ldsm4(u32* r, const __nv_bfloat16* p) {
    u32 a = (u32)__cvta_generic_to_shared(p);
    asm volatile("ldmatrix.sync.aligned.m8n8.x4.shared.b16 {%0,%1,%2,%3},[%4];"
                 : "=r"(r[0]), "=r"(r[1]), "=r"(r[2]), "=r"(r[3]) : "r"(a));
}

__device__ __forceinline__ void mma16816(float* d, const u32* a, u32 b0, u32 b1) {
    asm volatile("mma.sync.aligned.m16n8k16.row.col.f32.bf16.bf16.f32 "
                 "{%0,%1,%2,%3},{%4,%5,%6,%7},{%8,%9},{%0,%1,%2,%3};"
                 : "+f"(d[0]), "+f"(d[1]), "+f"(d[2]), "+f"(d[3])
                 : "r"(a[0]), "r"(a[1]), "r"(a[2]), "r"(a[3]), "r"(b0), "r"(b1));
}

__device__ __forceinline__ void cp16(void* dst, const void* src) {
    u32 d = (u32)__cvta_generic_to_shared(dst);
    asm volatile("cp.async.cg.shared.global [%0], [%1], 16;\n" :: "r"(d), "l"(src));
}

// ---------------- init ----------------
__global__ void k_init(const float* __restrict__ W_ih, const float* __restrict__ W_hh,
                       const float* __restrict__ b_ih, const float* __restrict__ b_hh,
                       const float* __restrict__ W_out) {
    size_t tid = (size_t)blockIdx.x * blockDim.x + threadIdx.x;
    size_t stride = (size_t)gridDim.x * blockDim.x;
    for (size_t i = tid; i < (size_t)VOCAB * HID; i += stride) {
        split2(W_out[i], &G_WHI[i], &G_WLO[i]);
    }
    for (size_t i = tid; i < (size_t)GATES * KCAT; i += stride) {
        int j = (int)(i / KCAT);
        int k = (int)(i - (size_t)j * KCAT);
        float v;
        if (k < HID) { v = W_ih[(size_t)j * HID + k]; }
        else         { v = W_hh[(size_t)j * HID + (k - HID)]; }
        split2(v, &G_WCHI[i], &G_WCLO[i]);
    }
    for (size_t i = tid; i < GATES; i += stride) { g_bgate[i] = b_ih[i] + b_hh[i]; }
    for (size_t i = tid; i < B * HID; i += stride) { g_h[i] = 0.f; g_c[i] = 0.f; }
    for (size_t i = tid; i < (size_t)B * GATES; i += stride) { g_gates[i] = 0.f; }
    if (tid < B) { g_key[tid] = (u64)(0xFFFFFFFFu - (u32)SOS); }
}

// prefetch ONE K16 HALF of a chunk into stage s: X 256 cp16 + W 768 cp16 = 4/thread
// half selects u4 columns {2h, 2h+1} of each 80B row (bytes [32h, 32h+32)).
__device__ __forceinline__ void pf_lhalf(uint4* Sm4, int nbase, int kc16, int s, int half, int tid) {
    int su = s * L_STG_U4;
    int cbase = half * 2;
    {
        int plane = tid >> 7;
        int idx = tid & 127;
        int r = idx >> 1;
        int col = (idx & 1) + cbase;
        const __nv_bfloat16* src = plane ? &G_HLO[r * HID + kc16 + (idx & 1) * 8]
                                         : &G_HHI[r * HID + kc16 + (idx & 1) * 8];
        cp16(&Sm4[su + plane * 320 + r * L_ROW_U4 + col], src);
    }
    #pragma unroll
    for (int e = 0; e < 3; e++) {
        int lin = tid + e * 256;
        int plane = (lin >= 384) ? 1 : 0;
        int idx = lin - plane * 384;
        int rr = idx >> 1;
        int col = (idx & 1) + cbase;
        int n = nbase + rr;
        if (n > VOCAB - 1) { n = VOCAB - 1; }
        const __nv_bfloat16* src = plane ? &G_WLO[(size_t)n * HID + kc16 + (idx & 1) * 8]
                                         : &G_WHI[(size_t)n * HID + kc16 + (idx & 1) * 8];
        cp16(&Sm4[su + 640 + plane * 960 + rr * L_ROW_U4 + col], src);
    }
    asm volatile("cp.async.commit_group;\n");
}

// ---------------- logits: C[64][VOCAB] = h @ W_out^T + b, fused argmax ----------------
// M64 x N192, 48 K16 half-iterations over a 4-half-slot ring (2 stages), wait_group(3).
__global__ void __launch_bounds__(256, 2) k_logits(const float* __restrict__ bias,
                                                   float* __restrict__ outStep) {
    extern __shared__ uint4 Sm4[];
    __shared__ u64 skey[64];
    const __nv_bfloat16* Sm = (const __nv_bfloat16*)Sm4;

    int tid = threadIdx.x;
    int w = tid >> 5;
    int l = tid & 31;
    int wm = w >> 2;                 // 0..1
    int wn = w & 3;                  // 0..3
    int nbase = blockIdx.x * 192;
    if (tid < 64) { skey[tid] = 0ull; }

    int sub = l >> 3;
    int arow = (sub & 1) * 8 + (l & 7);
    int acolo = (sub >> 1) * 8;
    int brow = (sub >> 1) * 8 + (l & 7);
    int bcolo = (sub & 1) * 8;

    float acc[2][6][4];
    #pragma unroll
    for (int i = 0; i < 2; i++) {
        #pragma unroll
        for (int j = 0; j < 6; j++) {
            #pragma unroll
            for (int q = 0; q < 4; q++) { acc[i][j][q] = 0.f; }
        }
    }

    // prologue: fill all 4 half-slots (chunks 0,1 = halves 0..3)
    pf_lhalf(Sm4, nbase, 0,  0, 0, tid);
    pf_lhalf(Sm4, nbase, 16, 0, 1, tid);
    pf_lhalf(Sm4, nbase, 32, 1, 0, tid);
    pf_lhalf(Sm4, nbase, 48, 1, 1, tid);

    #pragma unroll 1
    for (int i = 0; i < 48; i++) {
        // groups issued so far: min(48, i+4); require group i done
        int rem = 47 - i;
        if (rem >= 3) { asm volatile("cp.async.wait_group 3;\n"); }
        else if (rem == 2) { asm volatile("cp.async.wait_group 2;\n"); }
        else if (rem == 1) { asm volatile("cp.async.wait_group 1;\n"); }
        else { asm volatile("cp.async.wait_group 0;\n"); }
        __syncthreads();

        int s = (i >> 1) & 1;
        int kb = (i & 1) * 16;
        const __nv_bfloat16* Xb = Sm + s * L_STG_EL;
        const __nv_bfloat16* Wb = Sm + s * L_STG_EL + L_WHI;
        {
            u32 ah[2][4];
            u32 al[2][4];
            #pragma unroll
            for (int mt = 0; mt < 2; mt++) {
                int r = wm * 32 + mt * 16 + arow;
                ldsm4(ah[mt], Xb + r * L_ROW_EL + kb + acolo);
                ldsm4(al[mt], Xb + L_XLO + r * L_ROW_EL + kb + acolo);
            }
            u32 bh[3][4];
            u32 bl[3][4];
            #pragma unroll
            for (int ntp = 0; ntp < 3; ntp++) {
                int rw = wn * 48 + ntp * 16 + brow;
                ldsm4(bh[ntp], Wb + rw * L_ROW_EL + kb + bcolo);
                ldsm4(bl[ntp], Wb + L_WSPAN + rw * L_ROW_EL + kb + bcolo);
            }
            #pragma unroll
            for (int nt = 0; nt < 6; nt++) {
                int ntp = nt >> 1;
                int hf = (nt & 1) * 2;
                u32 h0 = bh[ntp][hf];
                u32 h1 = bh[ntp][hf + 1];
                u32 lo0 = bl[ntp][hf];
                u32 lo1 = bl[ntp][hf + 1];
                #pragma unroll
                for (int mt = 0; mt < 2; mt++) {
                    mma16816(acc[mt][nt], ah[mt], h0, h1);
                    mma16816(acc[mt][nt], ah[mt], lo0, lo1);
                    mma16816(acc[mt][nt], al[mt], h0, h1);
                }
            }
        }
        __syncthreads();   // all warps done reading half-slot i before overwrite
        if (i + 4 < 48) {
            int j = i + 4;
            pf_lhalf(Sm4, nbase, (j >> 1) * 32 + (j & 1) * 16, (j >> 1) & 1, j & 1, tid);
        }
    }

    // epilogue: bias + store + argmax keys
    #pragma unroll
    for (int mt = 0; mt < 2; mt++) {
        int r = wm * 32 + mt * 16 + (l >> 2);
        u64 k0 = 0ull;
        u64 k1 = 0ull;
        #pragma unroll
        for (int nt = 0; nt < 6; nt++) {
            int c0 = nbase + wn * 48 + nt * 8 + (l & 3) * 2;
            if (c0 + 1 < VOCAB) {
                const float2* bp = reinterpret_cast<const float2*>(&bias[c0]);
                float2 bb = bp[0];
                float v0 = acc[mt][nt][0] + bb.x;
                float v1 = acc[mt][nt][1] + bb.y;
                float v2 = acc[mt][nt][2] + bb.x;
                float v3 = acc[mt][nt][3] + bb.y;
                outStep[(long long)r * OSTRIDE + c0]           = v0;
                outStep[(long long)r * OSTRIDE + c0 + 1]       = v1;
                outStep[(long long)(r + 8) * OSTRIDE + c0]     = v2;
                outStep[(long long)(r + 8) * OSTRIDE + c0 + 1] = v3;
                u64 t;
                t = packKey(v0, c0);     if (t > k0) { k0 = t; }
                t = packKey(v1, c0 + 1); if (t > k0) { k0 = t; }
                t = packKey(v2, c0);     if (t > k1) { k1 = t; }
                t = packKey(v3, c0 + 1); if (t > k1) { k1 = t; }
            } else if (c0 < VOCAB) {
                float bb = bias[c0];
                float v0 = acc[mt][nt][0] + bb;
                float v2 = acc[mt][nt][2] + bb;
                outStep[(long long)r * OSTRIDE + c0]       = v0;
                outStep[(long long)(r + 8) * OSTRIDE + c0] = v2;
                u64 t;
                t = packKey(v0, c0); if (t > k0) { k0 = t; }
                t = packKey(v2, c0); if (t > k1) { k1 = t; }
            }
        }
        #pragma unroll
        for (int s = 1; s <= 2; s <<= 1) {
            u64 o0 = __shfl_xor_sync(0xFFFFFFFFu, k0, s);
            u64 o1 = __shfl_xor_sync(0xFFFFFFFFu, k1, s);
            if (o0 > k0) { k0 = o0; }
            if (o1 > k1) { k1 = o1; }
        }
        if ((l & 3) == 0) {
            atomicMax(&skey[r], k0);
            atomicMax(&skey[r + 8], k1);
        }
    }
    __syncthreads();
    if (tid < 64) {
        if (skey[tid] != 0ull) { atomicMax(&g_key[tid], skey[tid]); }
    }
}

// gather x[b][k] (k<HID: emb[tok], else h) -> split hi/lo uint4 (8 elems)
__device__ __forceinline__ void gatherx(int lm, int lk, int kc, const float* __restrict__ emb,
                                        const int* stoks, uint4& xh, uint4& xl) {
    int k = kc + lk;
    const float* src;
    if (k < HID) { src = emb + (size_t)stoks[lm] * HID + k; }
    else         { src = g_h + lm * HID + (k - HID); }
    float4 f0 = *reinterpret_cast<const float4*>(src);
    float4 f1 = *reinterpret_cast<const float4*>(src + 4);
    float v[8] = {f0.x, f0.y, f0.z, f0.w, f1.x, f1.y, f1.z, f1.w};
    u32 hw[4];
    u32 lw[4];
    #pragma unroll
    for (int e = 0; e < 4; e++) {
        __nv_bfloat16 h0, l0, h1, l1;
        split2(v[2 * e], &h0, &l0);
        split2(v[2 * e + 1], &h1, &l1);
        __nv_bfloat162 hp;
        hp.x = h0; hp.y = h1;
        __nv_bfloat162 lp;
        lp.x = l0; lp.y = l1;
        hw[e] = *reinterpret_cast<u32*>(&hp);
        lw[e] = *reinterpret_cast<u32*>(&lp);
    }
    xh = make_uint4(hw[0], hw[1], hw[2], hw[3]);
    xl = make_uint4(lw[0], lw[1], lw[2], lw[3]);
}

// prefetch one K64 chunk (gates): W via cp.async, X via gather+STS
__device__ __forceinline__ void pf_gates(uint4* Sm4, int nbase, int kc, int s, int tid,
                                         const float* __restrict__ emb, const int* stoks) {
    #pragma unroll
    for (int e = 0; e < 4; e++) {
        int lin = tid + e * 256;
        int row = lin >> 3;
        int cc = lin & 7;
        int n = nbase + row;
        cp16(&Sm4[s * STAGE_U4 + 1152 + row * ROW_U4 + cc], &G_WCHI[(size_t)n * KCAT + kc + cc * 8]);
        cp16(&Sm4[s * STAGE_U4 + 2304 + row * ROW_U4 + cc], &G_WCLO[(size_t)n * KCAT + kc + cc * 8]);
    }
    asm volatile("cp.async.commit_group;\n");
    #pragma unroll
    for (int e = 0; e < 2; e++) {
        int lin = tid + e * 256;
        int row = lin >> 3;
        int cc = lin & 7;
        uint4 xh, xl;
        gatherx(row, cc * 8, kc, emb, stoks, xh, xl);
        Sm4[s * STAGE_U4 + row * ROW_U4 + cc] = xh;
        Sm4[s * STAGE_U4 + 576 + row * ROW_U4 + cc] = xl;
    }
}

// ---------------- gates: g_gates[64][3072] += [emb|h] @ Wcat^T (+b on split 0) ----------------
__global__ void __launch_bounds__(256, 2) k_gates(const float* __restrict__ emb) {
    extern __shared__ uint4 Sm4[];
    __shared__ int stoks[64];
    const __nv_bfloat16* Sm = (const __nv_bfloat16*)Sm4;

    int tid = threadIdx.x;
    int w = tid >> 5;
    int l = tid & 31;
    int wm = w >> 2;
    int wn = w & 3;
    int nbase = blockIdx.x * 128;
    int kBegin = blockIdx.y * 192;

    if (tid < 64) {
        stoks[tid] = (int)(0xFFFFFFFFu - (u32)(g_key[tid] & 0xFFFFFFFFull));
    }
    __syncthreads();

    int sub = l >> 3;
    int arow = (sub & 1) * 8 + (l & 7);
    int acolo = (sub >> 1) * 8;
    int brow = (sub >> 1) * 8 + (l & 7);
    int bcolo = (sub & 1) * 8;

    float acc[2][4][4];
    #pragma unroll
    for (int i = 0; i < 2; i++) {
        #pragma unroll
        for (int j = 0; j < 4; j++) {
            #pragma unroll
            for (int q = 0; q < 4; q++) { acc[i][j][q] = 0.f; }
        }
    }

    pf_gates(Sm4, nbase, kBegin, 0, tid, emb, stoks);

    #pragma unroll 1
    for (int c = 0; c < 3; c++) {
        asm volatile("cp.async.wait_group 0;\n");
        __syncthreads();
        if (c < 2) { pf_gates(Sm4, nbase, kBegin + (c + 1) * 64, (c + 1) & 1, tid, emb, stoks); }

        int s = c & 1;
        const __nv_bfloat16* Xb = Sm + s * STAGE_EL;
        const __nv_bfloat16* Wb = Sm + s * STAGE_EL + WHI_EL;
        #pragma unroll
        for (int kk = 0; kk < 4; kk++) {
            int kb = kk * 16;
            u32 ah[2][4];
            u32 al[2][4];
            #pragma unroll
            for (int mt = 0; mt < 2; mt++) {
                int r = wm * 32 + mt * 16 + arow;
                ldsm4(ah[mt], Xb + r * ROW_ELEM + kb + acolo);
                ldsm4(al[mt], Xb + XLO_EL + r * ROW_ELEM + kb + acolo);
            }
            u32 bh[2][4];
            u32 bl[2][4];
            #pragma unroll
            for (int ntp = 0; ntp < 2; ntp++) {
                int r = wn * 32 + ntp * 16 + brow;
                ldsm4(bh[ntp], Wb + r * ROW_ELEM + kb + bcolo);
                ldsm4(bl[ntp], Wb + WHI_EL + r * ROW_ELEM + kb + bcolo);
            }
            #pragma unroll
            for (int nt = 0; nt < 4; nt++) {
                int ntp = nt >> 1;
                int hf = (nt & 1) * 2;
                u32 h0 = bh[ntp][hf];
                u32 h1 = bh[ntp][hf + 1];
                u32 lo0 = bl[ntp][hf];
                u32 lo1 = bl[ntp][hf + 1];
                #pragma unroll
                for (int mt = 0; mt < 2; mt++) {
                    mma16816(acc[mt][nt], ah[mt], h0, h1);
                    mma16816(acc[mt][nt], ah[mt], lo0, lo1);
                    mma16816(acc[mt][nt], al[mt], h0, h1);
                }
            }
        }
    }

    bool ab = (blockIdx.y == 0);
    #pragma unroll
    for (int mt = 0; mt < 2; mt++) {
        int r = wm * 32 + mt * 16 + (l >> 2);
        #pragma unroll
        for (int nt = 0; nt < 4; nt++) {
            int c0 = nbase + wn * 32 + nt * 8 + (l & 3) * 2;
            float bb0 = 0.f;
            float bb1 = 0.f;
            if (ab) { bb0 = g_bgate[c0]; bb1 = g_bgate[c0 + 1]; }
            atomicAdd(&g_gates[r * GATES + c0],           acc[mt][nt][0] + bb0);
            atomicAdd(&g_gates[r * GATES + c0 + 1],       acc[mt][nt][1] + bb1);
            atomicAdd(&g_gates[(r + 8) * GATES + c0],     acc[mt][nt][2] + bb0);
            atomicAdd(&g_gates[(r + 8) * GATES + c0 + 1], acc[mt][nt][3] + bb1);
        }
    }
}

// ---------------- LSTM cell update (float4) + zero gates + reset argmax ----------------
__global__ void k_update() {
    int idx = blockIdx.x * blockDim.x + threadIdx.x;
    if (idx < (B * HID) / 4) {
        int e = idx * 4;
        int b = e / HID;
        int j = e - b * HID;
        float* gr = &g_gates[b * GATES];
        float4 gi = *reinterpret_cast<float4*>(&gr[j]);
        float4 gf = *reinterpret_cast<float4*>(&gr[HID + j]);
        float4 gg = *reinterpret_cast<float4*>(&gr[2 * HID + j]);
        float4 go = *reinterpret_cast<float4*>(&gr[3 * HID + j]);
        float4 zz = make_float4(0.f, 0.f, 0.f, 0.f);
        *reinterpret_cast<float4*>(&gr[j]) = zz;
        *reinterpret_cast<float4*>(&gr[HID + j]) = zz;
        *reinterpret_cast<float4*>(&gr[2 * HID + j]) = zz;
        *reinterpret_cast<float4*>(&gr[3 * HID + j]) = zz;
        float4 cp = *reinterpret_cast<float4*>(&g_c[e]);
        float ia[4] = {gi.x, gi.y, gi.z, gi.w};
        float fa[4] = {gf.x, gf.y, gf.z, gf.w};
        float ga[4] = {gg.x, gg.y, gg.z, gg.w};
        float oa[4] = {go.x, go.y, go.z, go.w};
        float ca[4] = {cp.x, cp.y, cp.z, cp.w};
        float hn[4];
        float cn[4];
        #pragma unroll
        for (int q = 0; q < 4; q++) {
            float iv = 1.f / (1.f + expf(-ia[q]));
            float fv = 1.f / (1.f + expf(-fa[q]));
            float gv = tanhf(ga[q]);
            float ov = 1.f / (1.f + expf(-oa[q]));
            float c = fv * ca[q] + iv * gv;
            cn[q] = c;
            hn[q] = ov * tanhf(c);
        }
        *reinterpret_cast<float4*>(&g_c[e]) = make_float4(cn[0], cn[1], cn[2], cn[3]);
        *reinterpret_cast<float4*>(&g_h[e]) = make_float4(hn[0], hn[1], hn[2], hn[3]);
        #pragma unroll
        for (int q = 0; q < 4; q++) {
            split2(hn[q], &G_HHI[e + q], &G_HLO[e + q]);
        }
    }
    if (idx < B) { g_key[idx] = 0ull; }
}

__global__ void k_final(float* __restrict__ out) {
    int idx = blockIdx.x * blockDim.x + threadIdx.x;
    if (idx < B * HID) {
        out[idx]           = g_h[idx];
        out[B * HID + idx] = g_c[idx];
    }
}

extern "C" void kernel_launch(void* const* d_in, const int* in_sizes, int n_in,
                              void* d_out, int out_size) {
    const float* emb   = (const float*)d_in[1];
    const float* W_ih  = (const float*)d_in[2];
    const float* W_hh  = (const float*)d_in[3];
    const float* b_ih  = (const float*)d_in[4];
    const float* b_hh  = (const float*)d_in[5];
    const float* W_out = (const float*)d_in[6];
    const float* b_out = (const float*)d_in[7];
    float* out = (float*)d_out;

    cudaFuncSetAttribute(k_logits, cudaFuncAttributeMaxDynamicSharedMemorySize, DSMEM_L);
    cudaFuncSetAttribute(k_gates, cudaFuncAttributeMaxDynamicSharedMemorySize, DSMEM_G);

    k_init<<<2048, 256>>>(W_ih, W_hh, b_ih, b_hh, W_out);

    const long long logitsSize = (long long)B * MAXLEN * VOCAB;
    for (int t = 0; t < MAXLEN; t++) {
        k_gates<<<dim3(GATES / 128, 8), 256, DSMEM_G>>>(emb);
        k_update<<<48, 256>>>();
        k_logits<<<(VOCAB + 191) / 192, 256, DSMEM_L>>>(b_out, out + (long long)t * VOCAB);
    }
    if ((long long)out_size >= logitsSize + 2LL * B * HID) {
        k_final<<<192, 256>>>(out + logitsSize);
    }
}